// round 7
// baseline (speedup 1.0000x reference)
#include <cuda_runtime.h>
#include <cuda_bf16.h>

// TemporalConsistencyLoss — single kernel, block-role specialized (sm_103a).
//
// R7 vs R6 (42.0us, DRAM 47% / issue 38% / occ 53% -> latency-exposed):
//  - split the grid into MAIN blocks (ordering+BCE over all 4 batches,
//    128 MB streamed) and TRANS blocks (transitivity over the 16 MB
//    target_precedence[0] slice). Removes the fat b==0 branch from the
//    streaming loop -> fewer live regs, fewer instrs, higher occupancy.
//  - __ldcs evict-first for the streamed arrays.
//  - main loop unrolled x2 with both iterations' streaming loads hoisted.
//  - same per-block partial + ticket finalize (graph-replay safe).

#define S_DIM 2048
#define B_DIM 4
#define SS (S_DIM * S_DIM)              // 2^22
#define NTOT (B_DIM * SS)               // 2^24
#define NVEC (NTOT / 4)                 // 2^22 float4 units (main)
#define TVEC (SS / 4)                   // 2^20 float4 units (trans)
#define NBLK 1184                       // 148 SMs * 8 CTAs
#define TRANS_BLK 128                   // ~11% of blocks for ~11% of traffic
#define MAIN_BLK (NBLK - TRANS_BLK)     // 1056
#define NTHR 256

__device__ double g_part[NBLK][3];
__device__ unsigned int g_ticket;       // zero at module load; reset by last block

// ---- main path: ordering + BCE for one float4 group ----
__device__ __forceinline__ void main_math(
    int n, float4 p4, int4 t4,
    const float* __restrict__ pt, const float* __restrict__ tt,
    float& ord, float& bce)
{
    int rem = n & (SS - 1);
    int row = (n >> 22 << 11);           // b * S_DIM
    int i   = rem >> 11;
    int j   = rem & (S_DIM - 1);

    const float4 ptj = *reinterpret_cast<const float4*>(pt + row + j);
    const float4 ttj = *reinterpret_cast<const float4*>(tt + row + j);
    const float  pti = __ldg(pt + row + i);
    const float  tti = __ldg(tt + row + i);

    // BCE: log of product -> 1 MUFU per 4 elements (clamp preserved ~2e-7 rel)
    float v0 = t4.x ? p4.x : (1.0f - p4.x);
    float v1 = t4.y ? p4.y : (1.0f - p4.y);
    float v2 = t4.z ? p4.z : (1.0f - p4.z);
    float v3 = t4.w ? p4.w : (1.0f - p4.w);
    bce -= fmaxf(__logf((v0 * v1) * (v2 * v3)), -100.0f);

    // ordering hinge
    ord += (tti < ttj.x) ? fmaxf(0.5f - (pti - ptj.x), 0.0f) : 0.5f;
    ord += (tti < ttj.y) ? fmaxf(0.5f - (pti - ptj.y), 0.0f) : 0.5f;
    ord += (tti < ttj.z) ? fmaxf(0.5f - (pti - ptj.z), 0.0f) : 0.5f;
    ord += (tti < ttj.w) ? fmaxf(0.5f - (pti - ptj.w), 0.0f) : 0.5f;
}

__global__ void __launch_bounds__(NTHR, 6) tcl_fused_kernel(
    const float* __restrict__ pred_times,
    const float* __restrict__ pred_causal,
    const float* __restrict__ target_times,
    const int*   __restrict__ target_causal,
    const int*   __restrict__ target_prec,
    float* __restrict__ out, int out_size)
{
    const int tid = threadIdx.x;
    float ord = 0.0f, bce = 0.0f, tr = 0.0f;

    if (blockIdx.x < MAIN_BLK) {
        // ================= MAIN: ordering + BCE (128 MB stream) ============
        const int stride = MAIN_BLK * NTHR;         // 270336
        int v = blockIdx.x * NTHR + tid;
        #pragma unroll 1
        for (; v + stride < NVEC; v += 2 * stride) {
            int n0 = v << 2;
            int n1 = (v + stride) << 2;
            // hoist both iterations' streaming loads (4 outstanding LDG.128)
            const float4 pA = __ldcs(reinterpret_cast<const float4*>(pred_causal + n0));
            const int4   tA = __ldcs(reinterpret_cast<const int4*>(target_causal + n0));
            const float4 pB = __ldcs(reinterpret_cast<const float4*>(pred_causal + n1));
            const int4   tB = __ldcs(reinterpret_cast<const int4*>(target_causal + n1));
            main_math(n0, pA, tA, pred_times, target_times, ord, bce);
            main_math(n1, pB, tB, pred_times, target_times, ord, bce);
        }
        if (v < NVEC) {
            int n0 = v << 2;
            const float4 pA = __ldcs(reinterpret_cast<const float4*>(pred_causal + n0));
            const int4   tA = __ldcs(reinterpret_cast<const int4*>(target_causal + n0));
            main_math(n0, pA, tA, pred_times, target_times, ord, bce);
        }
    } else {
        // ================= TRANS: precedence[0] slice (16 MB stream) =======
        const int stride = TRANS_BLK * NTHR;        // 32768 -> exactly 32 iters
        int v = (blockIdx.x - MAIN_BLK) * NTHR + tid;
        #pragma unroll 1
        for (; v < TVEC; v += stride) {
            int rem = v << 2;
            int i   = rem >> 11;
            int j   = rem & (S_DIM - 1);

            const int4 pr = __ldcs(reinterpret_cast<const int4*>(target_prec + rem));
            const float4 q0 = *reinterpret_cast<const float4*>(pred_times + j);
            const float4 q1 = *reinterpret_cast<const float4*>(pred_times + S_DIM + j);
            const float4 q2 = *reinterpret_cast<const float4*>(pred_times + 2 * S_DIM + j);
            const float4 q3 = *reinterpret_cast<const float4*>(pred_times + 3 * S_DIM + j);
            const float i0 = __ldg(pred_times + i);
            const float i1 = __ldg(pred_times + S_DIM + i);
            const float i2 = __ldg(pred_times + 2 * S_DIM + i);
            const float i3 = __ldg(pred_times + 3 * S_DIM + i);

            const float qj[4][4] = {{q0.x, q1.x, q2.x, q3.x},
                                    {q0.y, q1.y, q2.y, q3.y},
                                    {q0.z, q1.z, q2.z, q3.z},
                                    {q0.w, q1.w, q2.w, q3.w}};
            const int prv[4] = {pr.x, pr.y, pr.z, pr.w};
            const int base_gap = j - i;

            #pragma unroll
            for (int l = 0; l < 4; l++) {
                int gap = base_gap + l;
                float w = (gap >= 2 && prv[l] != 0) ? (float)(gap - 1) : 0.0f;
                float s = fmaxf(0.1f - (qj[l][0] - i0), 0.0f)
                        + fmaxf(0.1f - (qj[l][1] - i1), 0.0f)
                        + fmaxf(0.1f - (qj[l][2] - i2), 0.0f)
                        + fmaxf(0.1f - (qj[l][3] - i3), 0.0f);
                tr += w * (s * 0.25f);
            }
        }
    }

    // ---- block reduction in double ----
    __shared__ double sh0[NTHR];
    __shared__ double sh1[NTHR];
    __shared__ double sh2[NTHR];
    sh0[tid] = (double)ord;
    sh1[tid] = (double)bce;
    sh2[tid] = (double)tr;
    __syncthreads();
    #pragma unroll
    for (int off = NTHR / 2; off > 0; off >>= 1) {
        if (tid < off) {
            sh0[tid] += sh0[tid + off];
            sh1[tid] += sh1[tid + off];
            sh2[tid] += sh2[tid + off];
        }
        __syncthreads();
    }

    // ---- write partial + ticket; dynamically-last block finalizes ----
    __shared__ bool s_is_last;
    if (tid == 0) {
        g_part[blockIdx.x][0] = sh0[0];
        g_part[blockIdx.x][1] = sh1[0];
        g_part[blockIdx.x][2] = sh2[0];
        __threadfence();
        unsigned int t = atomicAdd(&g_ticket, 1u);
        s_is_last = (t == (unsigned)(NBLK - 1));
    }
    __syncthreads();

    if (s_is_last) {
        double a0 = 0.0, a1 = 0.0, a2 = 0.0;
        for (int k = tid; k < NBLK; k += NTHR) {
            a0 += g_part[k][0];
            a1 += g_part[k][1];
            a2 += g_part[k][2];
        }
        sh0[tid] = a0; sh1[tid] = a1; sh2[tid] = a2;
        __syncthreads();
        #pragma unroll
        for (int off = NTHR / 2; off > 0; off >>= 1) {
            if (tid < off) {
                sh0[tid] += sh0[tid + off];
                sh1[tid] += sh1[tid + off];
                sh2[tid] += sh2[tid + off];
            }
            __syncthreads();
        }
        if (tid == 0) {
            const double N = (double)NTOT;
            double ordering  = sh0[0] / N;
            double causality = sh1[0] / N;
            const double denom = (double)S_DIM * (S_DIM - 1) * (S_DIM - 2) / 6.0;
            double transitivity = sh2[0] / denom;
            double total = ordering + 0.8 * causality + 0.6 * transitivity;
            if (out_size >= 4) {
                out[0] = (float)ordering;
                out[1] = (float)causality;
                out[2] = (float)transitivity;
                out[3] = (float)total;
            } else {
                out[0] = (float)total;
            }
            __threadfence();
            g_ticket = 0;   // reset for next graph replay
        }
    }
}

extern "C" void kernel_launch(void* const* d_in, const int* in_sizes, int n_in,
                              void* d_out, int out_size) {
    const float* pred_times    = (const float*)d_in[0];
    const float* pred_causal   = (const float*)d_in[1];
    const float* target_times  = (const float*)d_in[2];
    const int*   target_causal = (const int*)d_in[3];
    const int*   target_prec   = (const int*)d_in[4];
    float* out = (float*)d_out;

    tcl_fused_kernel<<<NBLK, NTHR>>>(pred_times, pred_causal, target_times,
                                     target_causal, target_prec, out, out_size);
}

// round 8
// speedup vs baseline: 1.3997x; 1.3997x over previous
#include <cuda_runtime.h>
#include <cuda_bf16.h>

// TemporalConsistencyLoss — single kernel, row-structured streaming (sm_103a).
//
// R8 vs R7 (55us regression) / R6 (42us):
//  - loop over rows: b, i, pti, tti, base pointers hoisted out of the element
//    loop; inner loop is exactly 2 float4 chunks per thread, loads hoisted.
//  - ZERO indexable local arrays (R6/R7 suspect: local-memory demotion of
//    qj[4][4]/pcv[4]/etc. inflating instruction count + L1 traffic).
//  - no __ldcs (R7's only other delta; correlated with DRAM% drop).
//  - transitivity via block-uniform b==0 row branch, all scalar math.
//  - per-block partials + ticket; last block finalizes (graph-replay safe).

#define S_DIM 2048
#define B_DIM 4
#define SS (S_DIM * S_DIM)              // 2^22
#define NTOT (B_DIM * SS)               // 2^24
#define ROWS_TOTAL (B_DIM * S_DIM)      // 8192
#define F4_ROW (S_DIM / 4)              // 512 float4 per row
#define NBLK 1184                       // 148 SMs * 8 CTAs
#define NTHR 256

__device__ double g_part[NBLK][3];
__device__ unsigned int g_ticket;       // zero at module load; reset by last block

// ordering + BCE for one float4 group (all scalars)
__device__ __forceinline__ void main_math(
    float4 p4, int4 t4, float4 ptj, float4 ttj, float pti, float tti,
    float& ord, float& bce)
{
    // BCE: log of product -> 1 MUFU per 4 elements (clamp preserved ~2e-7 rel)
    float v0 = t4.x ? p4.x : (1.0f - p4.x);
    float v1 = t4.y ? p4.y : (1.0f - p4.y);
    float v2 = t4.z ? p4.z : (1.0f - p4.z);
    float v3 = t4.w ? p4.w : (1.0f - p4.w);
    bce -= fmaxf(__logf((v0 * v1) * (v2 * v3)), -100.0f);

    // ordering hinge: relu(0.5 - td*torder); torder=0 -> 0.5
    float m;
    m = (tti < ttj.x) ? (pti - ptj.x) : 0.0f;  ord += fmaxf(0.5f - m, 0.0f);
    m = (tti < ttj.y) ? (pti - ptj.y) : 0.0f;  ord += fmaxf(0.5f - m, 0.0f);
    m = (tti < ttj.z) ? (pti - ptj.z) : 0.0f;  ord += fmaxf(0.5f - m, 0.0f);
    m = (tti < ttj.w) ? (pti - ptj.w) : 0.0f;  ord += fmaxf(0.5f - m, 0.0f);
}

// transitivity for one float4 group (accumulates w*s; 0.25 folded into finalize)
__device__ __forceinline__ void trans_math(
    int j, int i, int4 pr,
    float4 q0, float4 q1, float4 q2, float4 q3,
    float i0, float i1, float i2, float i3,
    float& tr)
{
    int g; float w, s;
    g = j - i;
    w = (g >= 2 && pr.x != 0) ? (float)(g - 1) : 0.0f;
    s = fmaxf(0.1f - (q0.x - i0), 0.0f) + fmaxf(0.1f - (q1.x - i1), 0.0f)
      + fmaxf(0.1f - (q2.x - i2), 0.0f) + fmaxf(0.1f - (q3.x - i3), 0.0f);
    tr += w * s;
    g = j + 1 - i;
    w = (g >= 2 && pr.y != 0) ? (float)(g - 1) : 0.0f;
    s = fmaxf(0.1f - (q0.y - i0), 0.0f) + fmaxf(0.1f - (q1.y - i1), 0.0f)
      + fmaxf(0.1f - (q2.y - i2), 0.0f) + fmaxf(0.1f - (q3.y - i3), 0.0f);
    tr += w * s;
    g = j + 2 - i;
    w = (g >= 2 && pr.z != 0) ? (float)(g - 1) : 0.0f;
    s = fmaxf(0.1f - (q0.z - i0), 0.0f) + fmaxf(0.1f - (q1.z - i1), 0.0f)
      + fmaxf(0.1f - (q2.z - i2), 0.0f) + fmaxf(0.1f - (q3.z - i3), 0.0f);
    tr += w * s;
    g = j + 3 - i;
    w = (g >= 2 && pr.w != 0) ? (float)(g - 1) : 0.0f;
    s = fmaxf(0.1f - (q0.w - i0), 0.0f) + fmaxf(0.1f - (q1.w - i1), 0.0f)
      + fmaxf(0.1f - (q2.w - i2), 0.0f) + fmaxf(0.1f - (q3.w - i3), 0.0f);
    tr += w * s;
}

__global__ void __launch_bounds__(NTHR) tcl_fused_kernel(
    const float* __restrict__ pred_times,
    const float* __restrict__ pred_causal,
    const float* __restrict__ target_times,
    const int*   __restrict__ target_causal,
    const int*   __restrict__ target_prec,
    float* __restrict__ out, int out_size)
{
    const int tid = threadIdx.x;
    float ord = 0.0f, bce = 0.0f, tr = 0.0f;

    const float4* __restrict__ pt4_all = reinterpret_cast<const float4*>(pred_times);
    const float4* __restrict__ tt4_all = reinterpret_cast<const float4*>(target_times);

    #pragma unroll 1
    for (int row = blockIdx.x; row < ROWS_TOTAL; row += NBLK) {
        const int b = row >> 11;
        const int i = row & (S_DIM - 1);
        const float pti = __ldg(pred_times + row);    // pt[b*S + i]
        const float tti = __ldg(target_times + row);

        const float4* __restrict__ pc4 = reinterpret_cast<const float4*>(pred_causal)   + (row << 9);
        const int4*   __restrict__ tc4 = reinterpret_cast<const int4*>(target_causal)   + (row << 9);
        const float4* __restrict__ pt4 = pt4_all + (b << 9);   // this batch's pt row
        const float4* __restrict__ tt4 = tt4_all + (b << 9);

        // two column chunks per thread; hoist streaming loads for MLP
        const float4 pA = pc4[tid];
        const int4   tA = tc4[tid];
        const float4 pB = pc4[tid + NTHR];
        const int4   tB = tc4[tid + NTHR];
        const float4 ptA = __ldg(pt4 + tid);
        const float4 ttA = __ldg(tt4 + tid);
        const float4 ptB = __ldg(pt4 + tid + NTHR);
        const float4 ttB = __ldg(tt4 + tid + NTHR);

        main_math(pA, tA, ptA, ttA, pti, tti, ord, bce);
        main_math(pB, tB, ptB, ttB, pti, tti, ord, bce);

        if (b == 0) {   // block-uniform branch: transitivity on prec[0] slice
            const int4* __restrict__ pr4 = reinterpret_cast<const int4*>(target_prec) + (i << 9);
            const int4 prA = pr4[tid];
            const int4 prB = pr4[tid + NTHR];
            const float i0 = pti;                                  // batch 0 == this row
            const float i1 = __ldg(pred_times + S_DIM + i);
            const float i2 = __ldg(pred_times + 2 * S_DIM + i);
            const float i3 = __ldg(pred_times + 3 * S_DIM + i);
            // batch rows at column chunk A (q0A == ptA since b==0)
            const float4 q1A = __ldg(pt4_all + (1 << 9) + tid);
            const float4 q2A = __ldg(pt4_all + (2 << 9) + tid);
            const float4 q3A = __ldg(pt4_all + (3 << 9) + tid);
            const float4 q1B = __ldg(pt4_all + (1 << 9) + tid + NTHR);
            const float4 q2B = __ldg(pt4_all + (2 << 9) + tid + NTHR);
            const float4 q3B = __ldg(pt4_all + (3 << 9) + tid + NTHR);

            trans_math(tid << 2, i, prA, ptA, q1A, q2A, q3A, i0, i1, i2, i3, tr);
            trans_math((tid + NTHR) << 2, i, prB, ptB, q1B, q2B, q3B, i0, i1, i2, i3, tr);
        }
    }

    // ---- block reduction in double ----
    __shared__ double sh0[NTHR];
    __shared__ double sh1[NTHR];
    __shared__ double sh2[NTHR];
    sh0[tid] = (double)ord;
    sh1[tid] = (double)bce;
    sh2[tid] = (double)tr;
    __syncthreads();
    #pragma unroll
    for (int off = NTHR / 2; off > 0; off >>= 1) {
        if (tid < off) {
            sh0[tid] += sh0[tid + off];
            sh1[tid] += sh1[tid + off];
            sh2[tid] += sh2[tid + off];
        }
        __syncthreads();
    }

    // ---- write partial + ticket; dynamically-last block finalizes ----
    __shared__ bool s_is_last;
    if (tid == 0) {
        g_part[blockIdx.x][0] = sh0[0];
        g_part[blockIdx.x][1] = sh1[0];
        g_part[blockIdx.x][2] = sh2[0];
        __threadfence();
        unsigned int t = atomicAdd(&g_ticket, 1u);
        s_is_last = (t == (unsigned)(NBLK - 1));
    }
    __syncthreads();

    if (s_is_last) {
        double a0 = 0.0, a1 = 0.0, a2 = 0.0;
        for (int k = tid; k < NBLK; k += NTHR) {
            a0 += g_part[k][0];
            a1 += g_part[k][1];
            a2 += g_part[k][2];
        }
        sh0[tid] = a0; sh1[tid] = a1; sh2[tid] = a2;
        __syncthreads();
        #pragma unroll
        for (int off = NTHR / 2; off > 0; off >>= 1) {
            if (tid < off) {
                sh0[tid] += sh0[tid + off];
                sh1[tid] += sh1[tid + off];
                sh2[tid] += sh2[tid + off];
            }
            __syncthreads();
        }
        if (tid == 0) {
            const double N = (double)NTOT;
            double ordering  = sh0[0] / N;
            double causality = sh1[0] / N;
            const double denom = (double)S_DIM * (S_DIM - 1) * (S_DIM - 2) / 6.0;
            double transitivity = (sh2[0] * 0.25) / denom;   // mean over B=4 folded here
            double total = ordering + 0.8 * causality + 0.6 * transitivity;
            if (out_size >= 4) {
                out[0] = (float)ordering;
                out[1] = (float)causality;
                out[2] = (float)transitivity;
                out[3] = (float)total;
            } else {
                out[0] = (float)total;
            }
            __threadfence();
            g_ticket = 0;   // reset for next graph replay
        }
    }
}

extern "C" void kernel_launch(void* const* d_in, const int* in_sizes, int n_in,
                              void* d_out, int out_size) {
    const float* pred_times    = (const float*)d_in[0];
    const float* pred_causal   = (const float*)d_in[1];
    const float* target_times  = (const float*)d_in[2];
    const int*   target_causal = (const int*)d_in[3];
    const int*   target_prec   = (const int*)d_in[4];
    float* out = (float*)d_out;

    tcl_fused_kernel<<<NBLK, NTHR>>>(pred_times, pred_causal, target_times,
                                     target_causal, target_prec, out, out_size);
}

// round 9
// speedup vs baseline: 1.5621x; 1.1160x over previous
#include <cuda_runtime.h>
#include <cuda_bf16.h>

// TemporalConsistencyLoss — batch-fixed blocks, register-resident row data.
//
// R9 vs R8 (39.4us, DRAM 50%/issue 35%/occ 53%):
//  - block's batch b is fixed -> ptj/ttj chunk loaded ONCE into registers
//    (was reloaded every row: ~half of all LSU work eliminated).
//  - phase-split transitivity over prec[0], q-chunks register-resident,
//    distributed across ALL blocks (no b==0 imbalance).
//  - 444 blocks x 512 thr = 148 SMs x 3 CTAs exactly; launch_bounds(512,3)
//    -> single wave, no static-assignment straggler tail.
//  - software-pipelined streaming loads (next row in flight during math).

#define S_DIM 2048
#define B_DIM 4
#define SS (S_DIM * S_DIM)              // 2^22
#define NTOT (B_DIM * SS)               // 2^24
#define NTHR 512
#define NBLK 444                        // 148 SMs * 3 CTAs
#define BLK_PER_B 111                   // NBLK / B_DIM

__device__ double g_part[NBLK][3];
__device__ unsigned int g_ticket;       // zero at module load; reset by last block

// ordering + BCE for one float4 group (all scalars)
__device__ __forceinline__ void main_math(
    float4 p4, int4 t4, float4 ptj, float4 ttj, float pti, float tti,
    float& ord, float& bce)
{
    // BCE: log of product -> 1 MUFU per 4 elements (clamp preserved ~2e-7 rel)
    float v0 = t4.x ? p4.x : (1.0f - p4.x);
    float v1 = t4.y ? p4.y : (1.0f - p4.y);
    float v2 = t4.z ? p4.z : (1.0f - p4.z);
    float v3 = t4.w ? p4.w : (1.0f - p4.w);
    bce -= fmaxf(__logf((v0 * v1) * (v2 * v3)), -100.0f);

    // ordering hinge: relu(0.5 - td*torder); torder=0 -> 0.5
    float m;
    m = (tti < ttj.x) ? (pti - ptj.x) : 0.0f;  ord += fmaxf(0.5f - m, 0.0f);
    m = (tti < ttj.y) ? (pti - ptj.y) : 0.0f;  ord += fmaxf(0.5f - m, 0.0f);
    m = (tti < ttj.z) ? (pti - ptj.z) : 0.0f;  ord += fmaxf(0.5f - m, 0.0f);
    m = (tti < ttj.w) ? (pti - ptj.w) : 0.0f;  ord += fmaxf(0.5f - m, 0.0f);
}

// transitivity for one float4 group (accumulates w*s; /4 folded into finalize)
__device__ __forceinline__ void trans_math(
    int j, int i, int4 pr,
    float4 q0, float4 q1, float4 q2, float4 q3,
    float i0, float i1, float i2, float i3,
    float& tr)
{
    int g; float w, s;
    g = j - i;
    w = (g >= 2 && pr.x != 0) ? (float)(g - 1) : 0.0f;
    s = fmaxf(0.1f - (q0.x - i0), 0.0f) + fmaxf(0.1f - (q1.x - i1), 0.0f)
      + fmaxf(0.1f - (q2.x - i2), 0.0f) + fmaxf(0.1f - (q3.x - i3), 0.0f);
    tr += w * s;
    g = j + 1 - i;
    w = (g >= 2 && pr.y != 0) ? (float)(g - 1) : 0.0f;
    s = fmaxf(0.1f - (q0.y - i0), 0.0f) + fmaxf(0.1f - (q1.y - i1), 0.0f)
      + fmaxf(0.1f - (q2.y - i2), 0.0f) + fmaxf(0.1f - (q3.y - i3), 0.0f);
    tr += w * s;
    g = j + 2 - i;
    w = (g >= 2 && pr.z != 0) ? (float)(g - 1) : 0.0f;
    s = fmaxf(0.1f - (q0.z - i0), 0.0f) + fmaxf(0.1f - (q1.z - i1), 0.0f)
      + fmaxf(0.1f - (q2.z - i2), 0.0f) + fmaxf(0.1f - (q3.z - i3), 0.0f);
    tr += w * s;
    g = j + 3 - i;
    w = (g >= 2 && pr.w != 0) ? (float)(g - 1) : 0.0f;
    s = fmaxf(0.1f - (q0.w - i0), 0.0f) + fmaxf(0.1f - (q1.w - i1), 0.0f)
      + fmaxf(0.1f - (q2.w - i2), 0.0f) + fmaxf(0.1f - (q3.w - i3), 0.0f);
    tr += w * s;
}

__global__ void __launch_bounds__(NTHR, 3) tcl_fused_kernel(
    const float* __restrict__ pred_times,
    const float* __restrict__ pred_causal,
    const float* __restrict__ target_times,
    const int*   __restrict__ target_causal,
    const int*   __restrict__ target_prec,
    float* __restrict__ out, int out_size)
{
    const int tid = threadIdx.x;
    const int bid = blockIdx.x;
    float ord = 0.0f, bce = 0.0f, tr = 0.0f;

    // ================= PHASE A: ordering + BCE (batch fixed) ================
    {
        const int b = bid / BLK_PER_B;       // 0..3, constant per block
        const int k = bid - b * BLK_PER_B;   // 0..110

        // loop-invariant: this thread's column chunk of pt/tt for batch b
        const float4* __restrict__ pt4 = reinterpret_cast<const float4*>(pred_times)   + (b << 9);
        const float4* __restrict__ tt4 = reinterpret_cast<const float4*>(target_times) + (b << 9);
        const float4 ptj = __ldg(pt4 + tid);
        const float4 ttj = __ldg(tt4 + tid);

        const float* __restrict__ ptrow = pred_times + (b << 11);
        const float* __restrict__ ttrow = target_times + (b << 11);
        const float4* __restrict__ pc4 = reinterpret_cast<const float4*>(pred_causal)  + (b << 20);
        const int4*   __restrict__ tc4 = reinterpret_cast<const int4*>(target_causal)  + (b << 20);

        // software pipeline over rows k, k+111, ... (<2048)
        int r = k;
        float4 pA = pc4[(r << 9) + tid];
        int4   tA = tc4[(r << 9) + tid];
        float pti = __ldg(ptrow + r);
        float tti = __ldg(ttrow + r);

        #pragma unroll 1
        for (;;) {
            const int rn = r + BLK_PER_B;
            const bool more = rn < S_DIM;
            float4 pA2; int4 tA2; float pti2, tti2;
            if (more) {
                pA2  = pc4[(rn << 9) + tid];
                tA2  = tc4[(rn << 9) + tid];
                pti2 = __ldg(ptrow + rn);
                tti2 = __ldg(ttrow + rn);
            }
            main_math(pA, tA, ptj, ttj, pti, tti, ord, bce);
            if (!more) break;
            pA = pA2; tA = tA2; pti = pti2; tti = tti2; r = rn;
        }
    }

    // ================= PHASE B: transitivity on prec[0] =====================
    {
        const float4* __restrict__ q4 = reinterpret_cast<const float4*>(pred_times);
        const float4 q0 = __ldg(q4 + tid);              // batch 0 row chunk
        const float4 q1 = __ldg(q4 + 512 + tid);
        const float4 q2 = __ldg(q4 + 1024 + tid);
        const float4 q3 = __ldg(q4 + 1536 + tid);
        const int4* __restrict__ pr4 = reinterpret_cast<const int4*>(target_prec);
        const int j = tid << 2;

        #pragma unroll 1
        for (int i = bid; i < S_DIM; i += NBLK) {
            const int4 pr = pr4[(i << 9) + tid];
            const float i0 = __ldg(pred_times + i);
            const float i1 = __ldg(pred_times + S_DIM + i);
            const float i2 = __ldg(pred_times + 2 * S_DIM + i);
            const float i3 = __ldg(pred_times + 3 * S_DIM + i);
            trans_math(j, i, pr, q0, q1, q2, q3, i0, i1, i2, i3, tr);
        }
    }

    // ---- block reduction in double ----
    __shared__ double sh0[NTHR];
    __shared__ double sh1[NTHR];
    __shared__ double sh2[NTHR];
    sh0[tid] = (double)ord;
    sh1[tid] = (double)bce;
    sh2[tid] = (double)tr;
    __syncthreads();
    #pragma unroll
    for (int off = NTHR / 2; off > 0; off >>= 1) {
        if (tid < off) {
            sh0[tid] += sh0[tid + off];
            sh1[tid] += sh1[tid + off];
            sh2[tid] += sh2[tid + off];
        }
        __syncthreads();
    }

    // ---- write partial + ticket; dynamically-last block finalizes ----
    __shared__ bool s_is_last;
    if (tid == 0) {
        g_part[bid][0] = sh0[0];
        g_part[bid][1] = sh1[0];
        g_part[bid][2] = sh2[0];
        __threadfence();
        unsigned int t = atomicAdd(&g_ticket, 1u);
        s_is_last = (t == (unsigned)(NBLK - 1));
    }
    __syncthreads();

    if (s_is_last) {
        double a0 = 0.0, a1 = 0.0, a2 = 0.0;
        for (int k2 = tid; k2 < NBLK; k2 += NTHR) {
            a0 += g_part[k2][0];
            a1 += g_part[k2][1];
            a2 += g_part[k2][2];
        }
        sh0[tid] = a0; sh1[tid] = a1; sh2[tid] = a2;
        __syncthreads();
        #pragma unroll
        for (int off = NTHR / 2; off > 0; off >>= 1) {
            if (tid < off) {
                sh0[tid] += sh0[tid + off];
                sh1[tid] += sh1[tid + off];
                sh2[tid] += sh2[tid + off];
            }
            __syncthreads();
        }
        if (tid == 0) {
            const double N = (double)NTOT;
            double ordering  = sh0[0] / N;
            double causality = sh1[0] / N;
            const double denom = (double)S_DIM * (S_DIM - 1) * (S_DIM - 2) / 6.0;
            double transitivity = (sh2[0] * 0.25) / denom;   // mean over B=4
            double total = ordering + 0.8 * causality + 0.6 * transitivity;
            if (out_size >= 4) {
                out[0] = (float)ordering;
                out[1] = (float)causality;
                out[2] = (float)transitivity;
                out[3] = (float)total;
            } else {
                out[0] = (float)total;
            }
            __threadfence();
            g_ticket = 0;   // reset for next graph replay
        }
    }
}

extern "C" void kernel_launch(void* const* d_in, const int* in_sizes, int n_in,
                              void* d_out, int out_size) {
    const float* pred_times    = (const float*)d_in[0];
    const float* pred_causal   = (const float*)d_in[1];
    const float* target_times  = (const float*)d_in[2];
    const int*   target_causal = (const int*)d_in[3];
    const int*   target_prec   = (const int*)d_in[4];
    float* out = (float*)d_out;

    tcl_fused_kernel<<<NBLK, NTHR>>>(pred_times, pred_causal, target_times,
                                     target_causal, target_prec, out, out_size);
}